// round 14
// baseline (speedup 1.0000x reference)
#include <cuda_runtime.h>
#include <cuda_bf16.h>
#include <cstdint>
#include <cfloat>

// Problem constants (fixed shapes)
#define B_  2
#define C_  32
#define T_  8
#define H_  32
#define W_  32
#define V_  8192
#define N_  16384          // B*T*H*W query rows
#define NELEM_ 524288      // B*C*T*H*W
#define THW_ 8192          // T*H*W
#define CAP_ 128           // global candidate capacity per row
#define RB_  48            // per-thread local candidate ring
#define CHC_ 256           // codes per staged chunk
#define NCH_ (V_ / CHC_)   // 32 chunks

typedef unsigned long long u64;
typedef unsigned int u32;

// ---------------- device scratch ----------------
__device__ int   g_q8[N_ * 8];       // packed int8 queries (8 words per row)
__device__ int   g_e8[V_ * 8];       // packed int8 codes (8 words per code)
__device__ int   g_heei[V_];         // round(0.5*||e||^2 * sq*se)
__device__ float g_hee[V_];          // 0.5*||e||^2 exact fp32 (rescore)
__device__ int   g_mi[N_];           // per-row integer margin (2x error bound)
__device__ u32   g_Mq_bits;          // max|f| bits
__device__ u32   g_Me_bits;          // max|emb| bits
__device__ u32   g_SAE_bits;         // max_c sum|e| bits
__device__ int   g_ccnt[N_];
__device__ int   g_cand[N_ * CAP_];
__device__ int   g_idx[N_];
__device__ int   g_counts[V_];
__device__ float g_g[NELEM_];
__device__ float g_loss;
__device__ int   g_used;

// ---------------- helpers ----------------
__device__ __forceinline__ int dp4a_s(int a, int b, int c) {
    int d;
    asm("dp4a.s32.s32 %0, %1, %2, %3;" : "=r"(d) : "r"(a), "r"(b), "r"(c));
    return d;
}
__device__ __forceinline__ void cpasync16(u32 smem, const void* gmem) {
    asm volatile("cp.async.cg.shared.global [%0], [%1], 16;" :: "r"(smem), "l"(gmem));
}
__device__ __forceinline__ void cpcommit() {
    asm volatile("cp.async.commit_group;");
}
__device__ __forceinline__ void cpwait0() {
    asm volatile("cp.async.wait_group 0;");
}
__device__ __forceinline__ u32 smem_u32(const void* p) {
    u32 a;
    asm("{ .reg .u64 t; cvta.to.shared.u64 t, %1; cvt.u32.u64 %0, t; }"
        : "=r"(a) : "l"(p));
    return a;
}
__device__ __forceinline__ int q8clamp(float v, float s) {
    int x = __float2int_rn(v * s);
    return max(-127, min(127, x));
}

// ---------------- init scalars ----------------
__global__ void init_kernel() {
    g_Mq_bits = 0; g_Me_bits = 0; g_SAE_bits = 0;
    g_loss = 0.f; g_used = 0;
}

// ---------------- prep 0: global abs-max of f and emb ----------------
__global__ void prep_max_kernel(const float* __restrict__ f,
                                const float* __restrict__ emb) {
    int tid = blockIdx.x * blockDim.x + threadIdx.x;
    float mq = 0.f, me = 0.f;
    for (int i = tid; i < NELEM_; i += gridDim.x * blockDim.x)
        mq = fmaxf(mq, fabsf(f[i]));
    for (int i = tid; i < V_ * C_; i += gridDim.x * blockDim.x)
        me = fmaxf(me, fabsf(emb[i]));
#pragma unroll
    for (int off = 16; off > 0; off >>= 1) {
        mq = fmaxf(mq, __shfl_xor_sync(0xffffffffu, mq, off));
        me = fmaxf(me, __shfl_xor_sync(0xffffffffu, me, off));
    }
    if ((threadIdx.x & 31) == 0) {
        atomicMax(&g_Mq_bits, __float_as_uint(mq));
        atomicMax(&g_Me_bits, __float_as_uint(me));
    }
}

// ---------------- prep 1: quantize codes, hee, SAE; zero counts ------------
__global__ void prep_e_kernel(const float* __restrict__ emb) {
    int code = blockIdx.x * blockDim.x + threadIdx.x;
    if (code >= V_) return;
    g_counts[code] = 0;
    const float sq = 127.f / fmaxf(__uint_as_float(g_Mq_bits), 1e-20f);
    const float se = 127.f / fmaxf(__uint_as_float(g_Me_bits), 1e-20f);
    const float* e = emb + code * C_;
    float ee = 0.f, sae = 0.f;
    int* dst = g_e8 + code * 8;
#pragma unroll
    for (int k = 0; k < 8; k++) {
        u32 pk = 0;
#pragma unroll
        for (int j = 0; j < 4; j++) {
            float v = e[4 * k + j];
            ee = fmaf(v, v, ee);
            sae += fabsf(v);
            pk |= ((u32)(q8clamp(v, se) & 0xFF)) << (8 * j);
        }
        dst[k] = (int)pk;
    }
    float hee = 0.5f * ee;
    g_hee[code] = hee;
    g_heei[code] = __float2int_rn(hee * sq * se);
    atomicMax(&g_SAE_bits, __float_as_uint(sae));
}

// ---------------- prep 2: quantize q rows + per-row int margin -------------
__global__ void prep_q_kernel(const float* __restrict__ f) {
    int row = blockIdx.x * blockDim.x + threadIdx.x;
    if (row >= N_) return;
    g_ccnt[row] = 0;
    const float Mq = fmaxf(__uint_as_float(g_Mq_bits), 1e-20f);
    const float Me = fmaxf(__uint_as_float(g_Me_bits), 1e-20f);
    const float sq = 127.f / Mq, se = 127.f / Me;
    const float* fq = f + (row >> 13) * (C_ * THW_) + (row & 8191);
    float sa = 0.f;
    int* dst = g_q8 + row * 8;
#pragma unroll
    for (int k = 0; k < 8; k++) {
        u32 pk = 0;
#pragma unroll
        for (int j = 0; j < 4; j++) {
            float v = fq[(4 * k + j) * THW_];
            sa += fabsf(v);
            pk |= ((u32)(q8clamp(v, sq) & 0xFF)) << (8 * j);
        }
        dst[k] = (int)pk;
    }
    const float dq = 0.5f / sq, de = 0.5f / se;
    const float SAE = __uint_as_float(g_SAE_bits);
    float margin = dq * SAE + de * sa + 32.f * dq * de;
    g_mi[row] = (int)ceilf(2.f * margin * sq * se) + 2;   // + hee rounding slack
}

// ---------------- fused sweep: running-max + local ring, final filter ------
// 256 threads = 32 rows x 8 partitions; grid = N/32 = 512 blocks.
// Warp = 32 lanes on the SAME partition -> broadcast LDS for codes.
__global__ __launch_bounds__(256) void sweep_kernel() {
    __shared__ __align__(16) int4 esc[2][CHC_ * 2];   // 2 x 8KB codes
    __shared__ __align__(16) int  esh[2][CHC_];       // 2 x 1KB hee_int
    __shared__ int rmax_s[256];

    const int tid = threadIdx.x;
    const int r = tid & 31;
    const int p = tid >> 5;
    const int row = blockIdx.x * 32 + r;

    int q8[8];
    {
        const int* qp = g_q8 + row * 8;
#pragma unroll
        for (int k = 0; k < 8; k++) q8[k] = qp[k];
    }
    const int mi = g_mi[row];

    int2 ring[RB_];     // local-memory candidate ring (code, int score)
    int rc = 0;

    const u32 scb = smem_u32(&esc[0][0]);
    const u32 shb = smem_u32(&esh[0][0]);

    // prefetch chunk 0
    {
        const uint4* src = reinterpret_cast<const uint4*>(g_e8);
#pragma unroll
        for (int i = 0; i < 2; i++) cpasync16(scb + (tid + 256 * i) * 16, src + tid + 256 * i);
        const uint4* hs = reinterpret_cast<const uint4*>(g_heei);
        if (tid < 64) cpasync16(shb + tid * 16, hs + tid);
        cpcommit();
    }

    int m = -(1 << 30);

#pragma unroll 1
    for (int ch = 0; ch < NCH_; ch++) {
        cpwait0();
        __syncthreads();
        if (ch + 1 < NCH_) {
            const uint4* src = reinterpret_cast<const uint4*>(g_e8 + (ch + 1) * (CHC_ * 8));
            u32 dst = scb + ((ch + 1) & 1) * (CHC_ * 32);
#pragma unroll
            for (int i = 0; i < 2; i++) cpasync16(dst + (tid + 256 * i) * 16, src + tid + 256 * i);
            const uint4* hs = reinterpret_cast<const uint4*>(g_heei + (ch + 1) * CHC_);
            if (tid < 64) cpasync16(shb + ((ch + 1) & 1) * (CHC_ * 4) + tid * 16, hs + tid);
            cpcommit();
        }
        const int4* bb = &esc[ch & 1][0];
        const int*  hh = &esh[ch & 1][0];
        const int cg0 = ch * CHC_ + p * 32;

#pragma unroll 2
        for (int j = 0; j < 8; j++) {
            const int c0 = p * 32 + 4 * j;
            int4 ea0 = bb[c0 * 2];
            int4 eb0 = bb[c0 * 2 + 1];
            int4 ea1 = bb[c0 * 2 + 2];
            int4 eb1 = bb[c0 * 2 + 3];
            int4 ea2 = bb[c0 * 2 + 4];
            int4 eb2 = bb[c0 * 2 + 5];
            int4 ea3 = bb[c0 * 2 + 6];
            int4 eb3 = bb[c0 * 2 + 7];
            int a0 = -hh[c0];
            int a1 = -hh[c0 + 1];
            int a2 = -hh[c0 + 2];
            int a3 = -hh[c0 + 3];
            a0 = dp4a_s(q8[0], ea0.x, a0);  a1 = dp4a_s(q8[0], ea1.x, a1);
            a2 = dp4a_s(q8[0], ea2.x, a2);  a3 = dp4a_s(q8[0], ea3.x, a3);
            a0 = dp4a_s(q8[1], ea0.y, a0);  a1 = dp4a_s(q8[1], ea1.y, a1);
            a2 = dp4a_s(q8[1], ea2.y, a2);  a3 = dp4a_s(q8[1], ea3.y, a3);
            a0 = dp4a_s(q8[2], ea0.z, a0);  a1 = dp4a_s(q8[2], ea1.z, a1);
            a2 = dp4a_s(q8[2], ea2.z, a2);  a3 = dp4a_s(q8[2], ea3.z, a3);
            a0 = dp4a_s(q8[3], ea0.w, a0);  a1 = dp4a_s(q8[3], ea1.w, a1);
            a2 = dp4a_s(q8[3], ea2.w, a2);  a3 = dp4a_s(q8[3], ea3.w, a3);
            a0 = dp4a_s(q8[4], eb0.x, a0);  a1 = dp4a_s(q8[4], eb1.x, a1);
            a2 = dp4a_s(q8[4], eb2.x, a2);  a3 = dp4a_s(q8[4], eb3.x, a3);
            a0 = dp4a_s(q8[5], eb0.y, a0);  a1 = dp4a_s(q8[5], eb1.y, a1);
            a2 = dp4a_s(q8[5], eb2.y, a2);  a3 = dp4a_s(q8[5], eb3.y, a3);
            a0 = dp4a_s(q8[6], eb0.z, a0);  a1 = dp4a_s(q8[6], eb1.z, a1);
            a2 = dp4a_s(q8[6], eb2.z, a2);  a3 = dp4a_s(q8[6], eb3.z, a3);
            a0 = dp4a_s(q8[7], eb0.w, a0);  a1 = dp4a_s(q8[7], eb1.w, a1);
            a2 = dp4a_s(q8[7], eb2.w, a2);  a3 = dp4a_s(q8[7], eb3.w, a3);

            const int thr = m - mi;     // running threshold (superset of sound set)
            if (a0 >= thr) {
                if (rc < RB_) { ring[rc] = make_int2(cg0 + 4 * j, a0); rc++; }
                else { int sl = atomicAdd(&g_ccnt[row], 1);
                       if (sl < CAP_) g_cand[row * CAP_ + sl] = cg0 + 4 * j; }
            }
            if (a1 >= thr) {
                if (rc < RB_) { ring[rc] = make_int2(cg0 + 4 * j + 1, a1); rc++; }
                else { int sl = atomicAdd(&g_ccnt[row], 1);
                       if (sl < CAP_) g_cand[row * CAP_ + sl] = cg0 + 4 * j + 1; }
            }
            if (a2 >= thr) {
                if (rc < RB_) { ring[rc] = make_int2(cg0 + 4 * j + 2, a2); rc++; }
                else { int sl = atomicAdd(&g_ccnt[row], 1);
                       if (sl < CAP_) g_cand[row * CAP_ + sl] = cg0 + 4 * j + 2; }
            }
            if (a3 >= thr) {
                if (rc < RB_) { ring[rc] = make_int2(cg0 + 4 * j + 3, a3); rc++; }
                else { int sl = atomicAdd(&g_ccnt[row], 1);
                       if (sl < CAP_) g_cand[row * CAP_ + sl] = cg0 + 4 * j + 3; }
            }
            m = max(m, max(max(a0, a1), max(a2, a3)));
        }
        __syncthreads();
    }

    // reduce row max across the 8 partitions
    rmax_s[tid] = m;
    __syncthreads();
    if (p == 0) {
        int mm = m;
#pragma unroll
        for (int k = 1; k < 8; k++) mm = max(mm, rmax_s[r + 32 * k]);
        rmax_s[r] = mm;
    }
    __syncthreads();
    const int thrF = rmax_s[r] - mi;

    // final filter: push only ring entries within margin of the ROW max
    for (int k = 0; k < rc; k++) {
        if (ring[k].y >= thrF) {
            int sl = atomicAdd(&g_ccnt[row], 1);
            if (sl < CAP_) g_cand[row * CAP_ + sl] = ring[k].x;
        }
    }
}

// ---------------- exact fp32 rescore of candidates ----------------
__global__ __launch_bounds__(256) void rescore_kernel(
    const float* __restrict__ f, const float* __restrict__ emb)
{
    const int row = blockIdx.x * 256 + threadIdx.x;
    const float* fq = f + (row >> 13) * (C_ * THW_) + (row & 8191);

    float q[32];
    float qq = 0.f;
#pragma unroll
    for (int ch = 0; ch < 32; ch++) {
        q[ch] = fq[ch * THW_];
        qq = fmaf(q[ch], q[ch], qq);
    }

    const int n = g_ccnt[row];
    float best = FLT_MAX;
    int bi = 0x7fffffff;

    if (n <= CAP_) {
        for (int k = 0; k < n; k++) {
            const int c = g_cand[row * CAP_ + k];
            const float* e = emb + c * C_;
            float dot = 0.f;
#pragma unroll
            for (int ch = 0; ch < 32; ch++) dot = fmaf(q[ch], e[ch], dot);
            float dist = fmaf(-2.f, dot, qq + 2.f * g_hee[c]);
            if (dist < best || (dist == best && c < bi)) { best = dist; bi = c; }
        }
    } else {
        for (int c = 0; c < V_; c++) {           // guaranteed-exact fallback
            const float* e = emb + c * C_;
            float dot = 0.f;
#pragma unroll
            for (int ch = 0; ch < 32; ch++) dot = fmaf(q[ch], e[ch], dot);
            float dist = fmaf(-2.f, dot, qq + 2.f * g_hee[c]);
            if (dist < best || (dist == best && c < bi)) { best = dist; bi = c; }
        }
    }

    g_idx[row] = bi;
    atomicAdd(&g_counts[bi], 1);
}

// ---------------- gather emb rows into NCDHW field ----------------
__global__ void gather_kernel(const float* __restrict__ emb) {
    int i = blockIdx.x * blockDim.x + threadIdx.x;
    if (i >= NELEM_) return;
    int b = i / (C_ * THW_);
    int c = (i / THW_) & (C_ - 1);
    int thw = i & (THW_ - 1);
    int rowq = b * THW_ + thw;
    g_g[i] = emb[g_idx[rowq] * C_ + c];
}

// ---------------- conv3d 3x3x3 SAME + blend + mse partial ----------------
// 256 blocks: (b, t, h-tile of 2). 512 threads = (w=32, hl=2, cog=8), 4 co each.
__global__ __launch_bounds__(512) void conv_kernel(
    const float* __restrict__ f, const float* __restrict__ cw,
    const float* __restrict__ cbias, float* __restrict__ out)
{
    __shared__ float ps[8 * 3 * 4 * 34];   // [cil][tt][hh][ww]  3264
    __shared__ float ws[8 * 27 * 32];      // 6912
    __shared__ float bias_s[32];
    __shared__ float red[16];

    const int tid = threadIdx.x;
    const int bi = blockIdx.x;
    const int ht = bi & 15;
    const int t  = (bi >> 4) & 7;
    const int b  = bi >> 7;
    const int h0 = ht * 2;
    const int w   = tid & 31;
    const int hl  = (tid >> 5) & 1;
    const int cog = tid >> 6;              // 0..7, co base = cog*4

    if (tid < 32) bias_s[tid] = cbias[tid];

    float acc[4];
#pragma unroll
    for (int i = 0; i < 4; i++) acc[i] = 0.f;

#pragma unroll 1
    for (int ci0 = 0; ci0 < 32; ci0 += 8) {
        __syncthreads();
        for (int i = tid; i < 8 * 3 * 4 * 34; i += 512) {
            int ww = i % 34;
            int r2 = i / 34;
            int hh = r2 % 4; r2 /= 4;
            int tt = r2 % 3;
            int cil = r2 / 3;
            int gt = t + tt - 1, gh = h0 + hh - 1, gw = ww - 1;
            float v = 0.f;
            if (gt >= 0 && gt < T_ && gh >= 0 && gh < H_ && gw >= 0 && gw < W_)
                v = g_g[b * (C_ * THW_) + (ci0 + cil) * THW_ + gt * 1024 + gh * 32 + gw];
            ps[i] = v;
        }
        for (int i = tid; i < 8 * 27 * 32; i += 512) {
            int co = i & 31;
            int r2 = i >> 5;
            int kk = r2 % 27;
            int cil = r2 / 27;
            ws[i] = cw[(co * 32 + ci0 + cil) * 27 + kk];
        }
        __syncthreads();

#pragma unroll 1
        for (int cil = 0; cil < 8; cil++) {
#pragma unroll 1
            for (int kt = 0; kt < 3; kt++) {
#pragma unroll
                for (int kh = 0; kh < 3; kh++) {
#pragma unroll
                    for (int kw = 0; kw < 3; kw++) {
                        float pv = ps[((cil * 3 + kt) * 4 + hl + kh) * 34 + w + kw];
                        const float4* wv = reinterpret_cast<const float4*>(
                            &ws[(cil * 27 + (kt * 9 + kh * 3 + kw)) * 32 + cog * 4]);
                        float4 w0 = wv[0];
                        acc[0] = fmaf(pv, w0.x, acc[0]);
                        acc[1] = fmaf(pv, w0.y, acc[1]);
                        acc[2] = fmaf(pv, w0.z, acc[2]);
                        acc[3] = fmaf(pv, w0.w, acc[3]);
                    }
                }
            }
        }
    }

    const int h = h0 + hl;
    float sq = 0.f;
    const int base = b * (C_ * THW_) + t * 1024 + h * 32 + w;
#pragma unroll
    for (int i = 0; i < 4; i++) {
        int co = cog * 4 + i;
        int o = base + co * THW_;
        float gv = g_g[o];
        float val = 0.5f * gv + 0.5f * (acc[i] + bias_s[co]);
        out[o] = val;
        float d = val - f[o];
        sq = fmaf(d, d, sq);
    }
#pragma unroll
    for (int off = 16; off > 0; off >>= 1)
        sq += __shfl_down_sync(0xffffffffu, sq, off);
    if ((tid & 31) == 0) red[tid >> 5] = sq;
    __syncthreads();
    if (tid == 0) {
        float s = 0.f;
#pragma unroll
        for (int i = 0; i < 16; i++) s += red[i];
        atomicAdd(&g_loss, s);
    }
}

// ---------------- usage count ----------------
__global__ void usage_kernel() {
    int v = blockIdx.x * blockDim.x + threadIdx.x;
    bool u = (v < V_) && (g_counts[v] > 0);
    unsigned m = __ballot_sync(0xffffffffu, u);
    if ((threadIdx.x & 31) == 0) atomicAdd(&g_used, __popc(m));
}

// ---------------- finalize scalars ----------------
__global__ void finalize_kernel(float* __restrict__ out, int write_scalars) {
    if (!write_scalars) return;
    out[NELEM_]     = 1.25f * g_loss * (1.0f / (float)NELEM_);
    out[NELEM_ + 1] = 100.0f * (float)g_used / (float)V_;
}

extern "C" void kernel_launch(void* const* d_in, const int* in_sizes, int n_in,
                              void* d_out, int out_size) {
    const float* f    = (const float*)d_in[0];
    const float* emb  = (const float*)d_in[1];
    const float* cw   = (const float*)d_in[2];
    const float* cb   = (const float*)d_in[3];
    float* out = (float*)d_out;
    int write_scalars = (out_size >= NELEM_ + 2) ? 1 : 0;

    init_kernel<<<1, 1>>>();
    prep_max_kernel<<<148, 256>>>(f, emb);
    prep_e_kernel<<<V_ / 256, 256>>>(emb);
    prep_q_kernel<<<N_ / 256, 256>>>(f);
    sweep_kernel<<<N_ / 32, 256>>>();
    rescore_kernel<<<N_ / 256, 256>>>(f, emb);
    gather_kernel<<<NELEM_ / 256, 256>>>(emb);
    conv_kernel<<<B_ * T_ * (H_ / 2), 512>>>(f, cw, cb, out);
    usage_kernel<<<V_ / 256, 256>>>();
    finalize_kernel<<<1, 1>>>(out, write_scalars);
}

// round 15
// speedup vs baseline: 1.0557x; 1.0557x over previous
#include <cuda_runtime.h>
#include <cuda_bf16.h>
#include <cstdint>
#include <cfloat>

// Problem constants (fixed shapes)
#define B_  2
#define C_  32
#define T_  8
#define H_  32
#define W_  32
#define V_  8192
#define N_  16384          // B*T*H*W query rows
#define NELEM_ 524288      // B*C*T*H*W
#define THW_ 8192          // T*H*W
#define CAP_ 128           // global candidate capacity per row
#define RB_  48            // per-thread local candidate ring
#define CHC_ 256           // codes per staged chunk
#define NCH_ (V_ / CHC_)   // 32 chunks

typedef unsigned long long u64;
typedef unsigned int u32;

// ---------------- device scratch ----------------
__device__ int   g_q8[N_ * 8];       // packed int8 queries (8 words per row)
__device__ int   g_e8[V_ * 8];       // packed int8 codes (8 words per code)
__device__ int   g_heei[V_];         // round(0.5*||e||^2 * sq*se)
__device__ float g_hee[V_];          // 0.5*||e||^2 exact fp32 (rescore)
__device__ int   g_mi[N_];           // per-row integer margin (2x error bound)
__device__ u32   g_Mq_bits;          // max|f| bits
__device__ u32   g_Me_bits;          // max|emb| bits
__device__ u32   g_SAE_bits;         // max_c sum|e| bits
__device__ int   g_ccnt[N_];
__device__ int   g_cand[N_ * CAP_];
__device__ int   g_idx[N_];
__device__ int   g_counts[V_];
__device__ float g_g[NELEM_];
__device__ float g_loss;
__device__ int   g_used;

// ---------------- helpers ----------------
__device__ __forceinline__ int dp4a_s(int a, int b, int c) {
    int d;
    asm("dp4a.s32.s32 %0, %1, %2, %3;" : "=r"(d) : "r"(a), "r"(b), "r"(c));
    return d;
}
__device__ __forceinline__ void cpasync16(u32 smem, const void* gmem) {
    asm volatile("cp.async.cg.shared.global [%0], [%1], 16;" :: "r"(smem), "l"(gmem));
}
__device__ __forceinline__ void cpcommit() {
    asm volatile("cp.async.commit_group;");
}
__device__ __forceinline__ void cpwait0() {
    asm volatile("cp.async.wait_group 0;");
}
__device__ __forceinline__ u32 smem_u32(const void* p) {
    u32 a;
    asm("{ .reg .u64 t; cvta.to.shared.u64 t, %1; cvt.u32.u64 %0, t; }"
        : "=r"(a) : "l"(p));
    return a;
}
__device__ __forceinline__ int q8clamp(float v, float s) {
    int x = __float2int_rn(v * s);
    return max(-127, min(127, x));
}

// ---------------- init scalars ----------------
__global__ void init_kernel() {
    g_Mq_bits = 0; g_Me_bits = 0; g_SAE_bits = 0;
    g_loss = 0.f; g_used = 0;
}

// ---------------- prep 0: global abs-max of f and emb ----------------
__global__ void prep_max_kernel(const float* __restrict__ f,
                                const float* __restrict__ emb) {
    int tid = blockIdx.x * blockDim.x + threadIdx.x;
    float mq = 0.f, me = 0.f;
    for (int i = tid; i < NELEM_; i += gridDim.x * blockDim.x)
        mq = fmaxf(mq, fabsf(f[i]));
    for (int i = tid; i < V_ * C_; i += gridDim.x * blockDim.x)
        me = fmaxf(me, fabsf(emb[i]));
#pragma unroll
    for (int off = 16; off > 0; off >>= 1) {
        mq = fmaxf(mq, __shfl_xor_sync(0xffffffffu, mq, off));
        me = fmaxf(me, __shfl_xor_sync(0xffffffffu, me, off));
    }
    if ((threadIdx.x & 31) == 0) {
        atomicMax(&g_Mq_bits, __float_as_uint(mq));
        atomicMax(&g_Me_bits, __float_as_uint(me));
    }
}

// ---------------- prep 1: quantize codes, hee, SAE; zero counts ------------
__global__ void prep_e_kernel(const float* __restrict__ emb) {
    int code = blockIdx.x * blockDim.x + threadIdx.x;
    if (code >= V_) return;
    g_counts[code] = 0;
    const float sq = 127.f / fmaxf(__uint_as_float(g_Mq_bits), 1e-20f);
    const float se = 127.f / fmaxf(__uint_as_float(g_Me_bits), 1e-20f);
    const float* e = emb + code * C_;
    float ee = 0.f, sae = 0.f;
    int* dst = g_e8 + code * 8;
#pragma unroll
    for (int k = 0; k < 8; k++) {
        u32 pk = 0;
#pragma unroll
        for (int j = 0; j < 4; j++) {
            float v = e[4 * k + j];
            ee = fmaf(v, v, ee);
            sae += fabsf(v);
            pk |= ((u32)(q8clamp(v, se) & 0xFF)) << (8 * j);
        }
        dst[k] = (int)pk;
    }
    float hee = 0.5f * ee;
    g_hee[code] = hee;
    g_heei[code] = __float2int_rn(hee * sq * se);
    atomicMax(&g_SAE_bits, __float_as_uint(sae));
}

// ---------------- prep 2: quantize q rows + per-row int margin -------------
__global__ void prep_q_kernel(const float* __restrict__ f) {
    int row = blockIdx.x * blockDim.x + threadIdx.x;
    if (row >= N_) return;
    g_ccnt[row] = 0;
    const float Mq = fmaxf(__uint_as_float(g_Mq_bits), 1e-20f);
    const float Me = fmaxf(__uint_as_float(g_Me_bits), 1e-20f);
    const float sq = 127.f / Mq, se = 127.f / Me;
    const float* fq = f + (row >> 13) * (C_ * THW_) + (row & 8191);
    float sa = 0.f;
    int* dst = g_q8 + row * 8;
#pragma unroll
    for (int k = 0; k < 8; k++) {
        u32 pk = 0;
#pragma unroll
        for (int j = 0; j < 4; j++) {
            float v = fq[(4 * k + j) * THW_];
            sa += fabsf(v);
            pk |= ((u32)(q8clamp(v, sq) & 0xFF)) << (8 * j);
        }
        dst[k] = (int)pk;
    }
    const float dq = 0.5f / sq, de = 0.5f / se;
    const float SAE = __uint_as_float(g_SAE_bits);
    float margin = dq * SAE + de * sa + 32.f * dq * de;
    g_mi[row] = (int)ceilf(2.f * margin * sq * se) + 2;   // + hee rounding slack
}

// ---------------- fused sweep: running-max + local ring, final filter ------
// 256 threads = 16 rows x 16 partitions; grid = N/16 = 1024 blocks (8192 warps).
// Partition p owns codes [p*16, p*16+16) of each 256-code chunk.
__global__ __launch_bounds__(256) void sweep_kernel() {
    __shared__ __align__(16) int4 esc[2][CHC_ * 2];   // 2 x 8KB codes
    __shared__ __align__(16) int  esh[2][CHC_];       // 2 x 1KB hee_int
    __shared__ int rmax_s[256];

    const int tid = threadIdx.x;
    const int r = tid & 15;
    const int p = tid >> 4;
    const int row = blockIdx.x * 16 + r;

    int q8[8];
    {
        const int* qp = g_q8 + row * 8;
#pragma unroll
        for (int k = 0; k < 8; k++) q8[k] = qp[k];
    }
    const int mi = g_mi[row];

    int2 ring[RB_];     // local-memory candidate ring (code, int score)
    int rc = 0;

    const u32 scb = smem_u32(&esc[0][0]);
    const u32 shb = smem_u32(&esh[0][0]);

    // prefetch chunk 0
    {
        const uint4* src = reinterpret_cast<const uint4*>(g_e8);
#pragma unroll
        for (int i = 0; i < 2; i++) cpasync16(scb + (tid + 256 * i) * 16, src + tid + 256 * i);
        const uint4* hs = reinterpret_cast<const uint4*>(g_heei);
        if (tid < 64) cpasync16(shb + tid * 16, hs + tid);
        cpcommit();
    }

    int m = -(1 << 30);

#pragma unroll 1
    for (int ch = 0; ch < NCH_; ch++) {
        cpwait0();
        __syncthreads();
        if (ch + 1 < NCH_) {
            const uint4* src = reinterpret_cast<const uint4*>(g_e8 + (ch + 1) * (CHC_ * 8));
            u32 dst = scb + ((ch + 1) & 1) * (CHC_ * 32);
#pragma unroll
            for (int i = 0; i < 2; i++) cpasync16(dst + (tid + 256 * i) * 16, src + tid + 256 * i);
            const uint4* hs = reinterpret_cast<const uint4*>(g_heei + (ch + 1) * CHC_);
            if (tid < 64) cpasync16(shb + ((ch + 1) & 1) * (CHC_ * 4) + tid * 16, hs + tid);
            cpcommit();
        }
        const int4* bb = &esc[ch & 1][0];
        const int*  hh = &esh[ch & 1][0];
        const int cg0 = ch * CHC_ + p * 16;

#pragma unroll 2
        for (int j = 0; j < 8; j++) {
            const int c0 = p * 16 + 2 * j;
            int4 ea0 = bb[c0 * 2];
            int4 eb0 = bb[c0 * 2 + 1];
            int4 ea1 = bb[c0 * 2 + 2];
            int4 eb1 = bb[c0 * 2 + 3];
            int acc0 = -hh[c0];
            int acc1 = -hh[c0 + 1];
            acc0 = dp4a_s(q8[0], ea0.x, acc0);  acc1 = dp4a_s(q8[0], ea1.x, acc1);
            acc0 = dp4a_s(q8[1], ea0.y, acc0);  acc1 = dp4a_s(q8[1], ea1.y, acc1);
            acc0 = dp4a_s(q8[2], ea0.z, acc0);  acc1 = dp4a_s(q8[2], ea1.z, acc1);
            acc0 = dp4a_s(q8[3], ea0.w, acc0);  acc1 = dp4a_s(q8[3], ea1.w, acc1);
            acc0 = dp4a_s(q8[4], eb0.x, acc0);  acc1 = dp4a_s(q8[4], eb1.x, acc1);
            acc0 = dp4a_s(q8[5], eb0.y, acc0);  acc1 = dp4a_s(q8[5], eb1.y, acc1);
            acc0 = dp4a_s(q8[6], eb0.z, acc0);  acc1 = dp4a_s(q8[6], eb1.z, acc1);
            acc0 = dp4a_s(q8[7], eb0.w, acc0);  acc1 = dp4a_s(q8[7], eb1.w, acc1);

            const int thr = m - mi;     // running threshold (superset of sound set)
            if (acc0 >= thr) {
                if (rc < RB_) { ring[rc] = make_int2(cg0 + 2 * j, acc0); rc++; }
                else {
                    int sl = atomicAdd(&g_ccnt[row], 1);
                    if (sl < CAP_) g_cand[row * CAP_ + sl] = cg0 + 2 * j;
                }
            }
            if (acc1 >= thr) {
                if (rc < RB_) { ring[rc] = make_int2(cg0 + 2 * j + 1, acc1); rc++; }
                else {
                    int sl = atomicAdd(&g_ccnt[row], 1);
                    if (sl < CAP_) g_cand[row * CAP_ + sl] = cg0 + 2 * j + 1;
                }
            }
            m = max(m, max(acc0, acc1));
        }
        __syncthreads();
    }

    // reduce row max across the 16 partitions
    rmax_s[tid] = m;
    __syncthreads();
    if (p == 0) {
        int mm = m;
#pragma unroll
        for (int k = 1; k < 16; k++) mm = max(mm, rmax_s[r + 16 * k]);
        rmax_s[r] = mm;
    }
    __syncthreads();
    const int thrF = rmax_s[r] - mi;

    // final filter: push only ring entries within margin of the ROW max
    for (int k = 0; k < rc; k++) {
        if (ring[k].y >= thrF) {
            int sl = atomicAdd(&g_ccnt[row], 1);
            if (sl < CAP_) g_cand[row * CAP_ + sl] = ring[k].x;
        }
    }
}

// ---------------- exact fp32 rescore of candidates ----------------
__global__ __launch_bounds__(256) void rescore_kernel(
    const float* __restrict__ f, const float* __restrict__ emb)
{
    const int row = blockIdx.x * 256 + threadIdx.x;
    const float* fq = f + (row >> 13) * (C_ * THW_) + (row & 8191);

    float q[32];
    float qq = 0.f;
#pragma unroll
    for (int ch = 0; ch < 32; ch++) {
        q[ch] = fq[ch * THW_];
        qq = fmaf(q[ch], q[ch], qq);
    }

    const int n = g_ccnt[row];
    float best = FLT_MAX;
    int bi = 0x7fffffff;

    if (n <= CAP_) {
        for (int k = 0; k < n; k++) {
            const int c = g_cand[row * CAP_ + k];
            const float* e = emb + c * C_;
            float dot = 0.f;
#pragma unroll
            for (int ch = 0; ch < 32; ch++) dot = fmaf(q[ch], e[ch], dot);
            float dist = fmaf(-2.f, dot, qq + 2.f * g_hee[c]);
            if (dist < best || (dist == best && c < bi)) { best = dist; bi = c; }
        }
    } else {
        for (int c = 0; c < V_; c++) {           // guaranteed-exact fallback
            const float* e = emb + c * C_;
            float dot = 0.f;
#pragma unroll
            for (int ch = 0; ch < 32; ch++) dot = fmaf(q[ch], e[ch], dot);
            float dist = fmaf(-2.f, dot, qq + 2.f * g_hee[c]);
            if (dist < best || (dist == best && c < bi)) { best = dist; bi = c; }
        }
    }

    g_idx[row] = bi;
    atomicAdd(&g_counts[bi], 1);
}

// ---------------- gather emb rows into NCDHW field ----------------
__global__ void gather_kernel(const float* __restrict__ emb) {
    int i = blockIdx.x * blockDim.x + threadIdx.x;
    if (i >= NELEM_) return;
    int b = i / (C_ * THW_);
    int c = (i / THW_) & (C_ - 1);
    int thw = i & (THW_ - 1);
    int rowq = b * THW_ + thw;
    g_g[i] = emb[g_idx[rowq] * C_ + c];
}

// ---------------- conv3d 3x3x3 SAME + blend + mse partial ----------------
// 256 blocks: (b, t, h-tile of 2). 256 threads = (w=32, hl=2, cog=4), 8 co each.
__global__ __launch_bounds__(256) void conv_kernel(
    const float* __restrict__ f, const float* __restrict__ cw,
    const float* __restrict__ cbias, float* __restrict__ out)
{
    __shared__ float ps[8 * 3 * 4 * 34];   // [cil][tt][hh][ww]  3264
    __shared__ float ws[8 * 27 * 32];      // 6912
    __shared__ float bias_s[32];
    __shared__ float red[8];

    const int tid = threadIdx.x;
    const int bi = blockIdx.x;
    const int ht = bi & 15;
    const int t  = (bi >> 4) & 7;
    const int b  = bi >> 7;
    const int h0 = ht * 2;
    const int w   = tid & 31;
    const int hl  = (tid >> 5) & 1;
    const int cog = tid >> 6;

    if (tid < 32) bias_s[tid] = cbias[tid];

    float acc[8];
#pragma unroll
    for (int i = 0; i < 8; i++) acc[i] = 0.f;

#pragma unroll 1
    for (int ci0 = 0; ci0 < 32; ci0 += 8) {
        __syncthreads();
        for (int i = tid; i < 8 * 3 * 4 * 34; i += 256) {
            int ww = i % 34;
            int r2 = i / 34;
            int hh = r2 % 4; r2 /= 4;
            int tt = r2 % 3;
            int cil = r2 / 3;
            int gt = t + tt - 1, gh = h0 + hh - 1, gw = ww - 1;
            float v = 0.f;
            if (gt >= 0 && gt < T_ && gh >= 0 && gh < H_ && gw >= 0 && gw < W_)
                v = g_g[b * (C_ * THW_) + (ci0 + cil) * THW_ + gt * 1024 + gh * 32 + gw];
            ps[i] = v;
        }
        for (int i = tid; i < 8 * 27 * 32; i += 256) {
            int co = i & 31;
            int r2 = i >> 5;
            int kk = r2 % 27;
            int cil = r2 / 27;
            ws[i] = cw[(co * 32 + ci0 + cil) * 27 + kk];
        }
        __syncthreads();

#pragma unroll 1
        for (int cil = 0; cil < 8; cil++) {
#pragma unroll 1
            for (int kt = 0; kt < 3; kt++) {
#pragma unroll
                for (int kh = 0; kh < 3; kh++) {
#pragma unroll
                    for (int kw = 0; kw < 3; kw++) {
                        float pv = ps[((cil * 3 + kt) * 4 + hl + kh) * 34 + w + kw];
                        const float4* wv = reinterpret_cast<const float4*>(
                            &ws[(cil * 27 + (kt * 9 + kh * 3 + kw)) * 32 + cog * 8]);
                        float4 w0 = wv[0];
                        float4 w1 = wv[1];
                        acc[0] = fmaf(pv, w0.x, acc[0]);
                        acc[1] = fmaf(pv, w0.y, acc[1]);
                        acc[2] = fmaf(pv, w0.z, acc[2]);
                        acc[3] = fmaf(pv, w0.w, acc[3]);
                        acc[4] = fmaf(pv, w1.x, acc[4]);
                        acc[5] = fmaf(pv, w1.y, acc[5]);
                        acc[6] = fmaf(pv, w1.z, acc[6]);
                        acc[7] = fmaf(pv, w1.w, acc[7]);
                    }
                }
            }
        }
    }

    const int h = h0 + hl;
    float sq = 0.f;
    const int base = b * (C_ * THW_) + t * 1024 + h * 32 + w;
#pragma unroll
    for (int i = 0; i < 8; i++) {
        int co = cog * 8 + i;
        int o = base + co * THW_;
        float gv = g_g[o];
        float val = 0.5f * gv + 0.5f * (acc[i] + bias_s[co]);
        out[o] = val;
        float d = val - f[o];
        sq = fmaf(d, d, sq);
    }
#pragma unroll
    for (int off = 16; off > 0; off >>= 1)
        sq += __shfl_down_sync(0xffffffffu, sq, off);
    if ((tid & 31) == 0) red[tid >> 5] = sq;
    __syncthreads();
    if (tid == 0) {
        float s = 0.f;
#pragma unroll
        for (int i = 0; i < 8; i++) s += red[i];
        atomicAdd(&g_loss, s);
    }
}

// ---------------- usage count ----------------
__global__ void usage_kernel() {
    int v = blockIdx.x * blockDim.x + threadIdx.x;
    bool u = (v < V_) && (g_counts[v] > 0);
    unsigned m = __ballot_sync(0xffffffffu, u);
    if ((threadIdx.x & 31) == 0) atomicAdd(&g_used, __popc(m));
}

// ---------------- finalize scalars ----------------
__global__ void finalize_kernel(float* __restrict__ out, int write_scalars) {
    if (!write_scalars) return;
    out[NELEM_]     = 1.25f * g_loss * (1.0f / (float)NELEM_);
    out[NELEM_ + 1] = 100.0f * (float)g_used / (float)V_;
}

extern "C" void kernel_launch(void* const* d_in, const int* in_sizes, int n_in,
                              void* d_out, int out_size) {
    const float* f    = (const float*)d_in[0];
    const float* emb  = (const float*)d_in[1];
    const float* cw   = (const float*)d_in[2];
    const float* cb   = (const float*)d_in[3];
    float* out = (float*)d_out;
    int write_scalars = (out_size >= NELEM_ + 2) ? 1 : 0;

    init_kernel<<<1, 1>>>();
    prep_max_kernel<<<148, 256>>>(f, emb);
    prep_e_kernel<<<V_ / 256, 256>>>(emb);
    prep_q_kernel<<<N_ / 256, 256>>>(f);
    sweep_kernel<<<N_ / 16, 256>>>();
    rescore_kernel<<<N_ / 256, 256>>>(f, emb);
    gather_kernel<<<NELEM_ / 256, 256>>>(emb);
    conv_kernel<<<B_ * T_ * (H_ / 2), 256>>>(f, cw, cb, out);
    usage_kernel<<<V_ / 256, 256>>>();
    finalize_kernel<<<1, 1>>>(out, write_scalars);
}